// round 13
// baseline (speedup 1.0000x reference)
#include <cuda_runtime.h>
#include <cuda_bf16.h>
#include <cstdint>

// LinearMPC via mma.sync bf16 split hi/lo — CTA-local, no clusters, no cp.async.
// u <- clip(u - s(uH + f)), 100 iters, B=2048, M=512, H symmetric.
// R13: BT=32 batches/CTA (64 CTAs) halves chip-wide H L2 traffic vs R11.
// H streamed L2->regs via LDG.64 (packed hi|lo words, PRMT decode),
// register double-buffered; u packed in SMEM only; 2 barriers/iter.

#define MD 512
#define BATCH 2048
#define BT 32
#define ITERS 100
#define STEPC 0.01f
#define THREADS 512
#define USTR 2080u            // u_s / f_s row stride bytes (520 words)
#define F_OFF 66560u          // f_s offset = 32*USTR
#define SMEM_TOTAL 133120

__device__ __align__(16) float    g_f [BATCH * MD];
__device__ __align__(16) uint32_t g_hp[MD * MD];     // (bf16hi<<16)|bf16lo

__device__ __forceinline__ uint32_t prmt(uint32_t a, uint32_t b, uint32_t s) {
    uint32_t d;
    asm("prmt.b32 %0, %1, %2, %3;" : "=r"(d) : "r"(a), "r"(b), "r"(s));
    return d;
}
__device__ __forceinline__ void mma4(float* d, const uint32_t* a,
                                     const uint32_t* b) {
    asm volatile(
        "mma.sync.aligned.m16n8k16.row.col.f32.bf16.bf16.f32 "
        "{%0,%1,%2,%3}, {%4,%5,%6,%7}, {%8,%9}, {%0,%1,%2,%3};"
        : "+f"(d[0]), "+f"(d[1]), "+f"(d[2]), "+f"(d[3])
        : "r"(a[0]), "r"(a[1]), "r"(a[2]), "r"(a[3]), "r"(b[0]), "r"(b[1]));
}
__device__ __forceinline__ float clamp1(float x) {
    return fminf(fmaxf(x, -1.0f), 1.0f);
}
__device__ __forceinline__ uint32_t pack_u(float v) {
    __nv_bfloat16 h = __float2bfloat16(v);
    __nv_bfloat16 l = __float2bfloat16(v - __bfloat162float(h));
    return ((uint32_t)__bfloat16_as_ushort(h) << 16)
         | (uint32_t)__bfloat16_as_ushort(l);
}
__device__ __forceinline__ float dec(uint32_t w) {
    return __bfloat162float(__ushort_as_bfloat16((unsigned short)(w >> 16)))
         + __bfloat162float(__ushort_as_bfloat16((unsigned short)(w & 0xFFFFu)));
}

// Prologue 1: f[b, k*8+i] = -2 * Phi[k] @ Q @ (xref[b,k] - xref[b,0])
__global__ void mpc_f_kernel(const float* __restrict__ xref,
                             const float* __restrict__ Phi,
                             const float* __restrict__ Q) {
    int b = blockIdx.x * 4 + threadIdx.y;
    int k = threadIdx.x;
    const float* xr = xref + (size_t)b * 65 * 8;
    float dx[8], t[8];
#pragma unroll
    for (int l = 0; l < 8; l++) dx[l] = xr[k * 8 + l] - xr[l];
#pragma unroll
    for (int j = 0; j < 8; j++) {
        float s = 0.f;
#pragma unroll
        for (int l = 0; l < 8; l++) s = fmaf(Q[j * 8 + l], dx[l], s);
        t[j] = s;
    }
    const float* Pk = Phi + (size_t)k * 64;
#pragma unroll
    for (int i = 0; i < 8; i++) {
        float s = 0.f;
#pragma unroll
        for (int j = 0; j < 8; j++) s = fmaf(Pk[i * 8 + j], t[j], s);
        g_f[(size_t)b * MD + k * 8 + i] = -2.0f * s;
    }
}

// Prologue 2: pack H fp32 -> (bf16hi<<16)|bf16lo words.
__global__ void mpc_hpack_kernel(const float* __restrict__ Hm) {
    int i = blockIdx.x * 256 + threadIdx.x;
    g_hp[i] = pack_u(Hm[i]);
}

// B-fragment prefetch for one 16-k chunk into register buffer BUF[4][2].
// Warp w owns H rows [32w, 32w+32); mf-block stride 8 rows = 2048 uint2.
#define PREFETCH(BUF, KC_)                                                    \
    {                                                                         \
        const uint2* hp_ = (const uint2*)(g_hp + hbase0 +                     \
                                          (uint32_t)(((KC_) & 31) * 16));     \
        _Pragma("unroll")                                                     \
        for (int mf_ = 0; mf_ < 4; mf_++) {                                   \
            BUF[mf_][0] = __ldg(hp_ + mf_ * 2048);                            \
            BUF[mf_][1] = __ldg(hp_ + mf_ * 2048 + 4);                        \
        }                                                                     \
    }

// One 16-k chunk: decode B once, then both batch-frags; 24 MMAs.
#define COMPUTE(BUF, KC_)                                                     \
    {                                                                         \
        uint32_t bh[4][2], bl[4][2];                                          \
        _Pragma("unroll")                                                     \
        for (int mf_ = 0; mf_ < 4; mf_++) {                                   \
            bh[mf_][0] = prmt(BUF[mf_][0].x, BUF[mf_][0].y, 0x7632u);         \
            bl[mf_][0] = prmt(BUF[mf_][0].x, BUF[mf_][0].y, 0x5410u);         \
            bh[mf_][1] = prmt(BUF[mf_][1].x, BUF[mf_][1].y, 0x7632u);         \
            bl[mf_][1] = prmt(BUF[mf_][1].x, BUF[mf_][1].y, 0x5410u);         \
        }                                                                     \
        _Pragma("unroll")                                                     \
        for (int bf_ = 0; bf_ < 2; bf_++) {                                   \
            const uint32_t ub_ = uAb + (uint32_t)bf_ * (16u * USTR)           \
                                 + (uint32_t)((KC_) & 31) * 64u;              \
            uint2 wa0 = *(const uint2*)(smem + ub_);                          \
            uint2 wa2 = *(const uint2*)(smem + ub_ + 32u);                    \
            uint2 wa1 = *(const uint2*)(smem + ub_ + 8u * USTR);              \
            uint2 wa3 = *(const uint2*)(smem + ub_ + 8u * USTR + 32u);        \
            uint32_t ah[4], al[4];                                            \
            ah[0] = prmt(wa0.x, wa0.y, 0x7632u); al[0] = prmt(wa0.x, wa0.y, 0x5410u); \
            ah[1] = prmt(wa1.x, wa1.y, 0x7632u); al[1] = prmt(wa1.x, wa1.y, 0x5410u); \
            ah[2] = prmt(wa2.x, wa2.y, 0x7632u); al[2] = prmt(wa2.x, wa2.y, 0x5410u); \
            ah[3] = prmt(wa3.x, wa3.y, 0x7632u); al[3] = prmt(wa3.x, wa3.y, 0x5410u); \
            _Pragma("unroll")                                                 \
            for (int mf_ = 0; mf_ < 4; mf_++) {                               \
                float* d_ = acc[bf_][mf_];                                    \
                mma4(d_, ah, bh[mf_]);                                        \
                mma4(d_, al, bh[mf_]);                                        \
                mma4(d_, ah, bl[mf_]);                                        \
            }                                                                 \
        }                                                                     \
    }

__global__ void __launch_bounds__(THREADS, 1)
mpc_mma_kernel(float* __restrict__ out) {
    extern __shared__ char smem[];   // u_s [32][520w] @0; f_s [32][520f] @F_OFF
    const int tid = threadIdx.x, lane = tid & 31;
    const int qr = lane >> 2, qc = lane & 3;
    const int w = tid >> 5;
    const int m0w = w * 32;                 // warp's 32-wide m-slice
    const int cb = blockIdx.x * BT;

    // Stage f.
    for (int i = tid; i < BT * MD; i += THREADS) {
        int b = i >> 9, m = i & (MD - 1);
        *(float*)(smem + F_OFF + (uint32_t)b * USTR + (uint32_t)m * 4u) =
            g_f[(size_t)(cb + b) * MD + m];
    }
    __syncthreads();

    // Iteration 0: u1 = clip(-s*f), write packed u_s.
#pragma unroll
    for (int bf = 0; bf < 2; bf++) {
        uint32_t r0 = (uint32_t)(16 * bf + qr) * USTR;
#pragma unroll
        for (int mf = 0; mf < 4; mf++) {
            int mcol = m0w + 8 * mf + 2 * qc;
            float2 f0 = *(float2*)(smem + F_OFF + r0 + mcol * 4);
            float2 f1 = *(float2*)(smem + F_OFF + r0 + 8 * USTR + mcol * 4);
            *(uint2*)(smem + r0 + mcol * 4) =
                make_uint2(pack_u(clamp1(-STEPC * f0.x)),
                           pack_u(clamp1(-STEPC * f0.y)));
            *(uint2*)(smem + r0 + 8 * USTR + mcol * 4) =
                make_uint2(pack_u(clamp1(-STEPC * f1.x)),
                           pack_u(clamp1(-STEPC * f1.y)));
        }
    }
    __syncthreads();

    // Per-lane constant offsets.
    const uint32_t hbase0 = (uint32_t)(m0w + qr) * 512u + 2u * qc;   // word idx
    const uint32_t uAb = (uint32_t)qr * USTR + 8u * qc;              // byte

    uint2 B0[4][2], B1[4][2];
    PREFETCH(B0, 0);
    PREFETCH(B1, 1);

    for (int it = 1; it < ITERS; it++) {
        float acc[2][4][4];
#pragma unroll
        for (int bf = 0; bf < 2; bf++) {
            uint32_t r0 = F_OFF + (uint32_t)(16 * bf + qr) * USTR;
#pragma unroll
            for (int mf = 0; mf < 4; mf++) {
                int mcol = m0w + 8 * mf + 2 * qc;
                float2 f0 = *(float2*)(smem + r0 + mcol * 4);
                float2 f1 = *(float2*)(smem + r0 + 8 * USTR + mcol * 4);
                acc[bf][mf][0] = f0.x; acc[bf][mf][1] = f0.y;
                acc[bf][mf][2] = f1.x; acc[bf][mf][3] = f1.y;
            }
        }

#pragma unroll 1
        for (int kc = 0; kc < 32; kc += 2) {
            COMPUTE(B0, kc);
            PREFETCH(B0, kc + 2);     // wraps: prefetches next iter's chunk 0/1
            COMPUTE(B1, kc + 1);
            PREFETCH(B1, kc + 3);
        }

        __syncthreads();   // all warps done reading u_s this iteration

        const bool last = (it == ITERS - 1);
#pragma unroll
        for (int bf = 0; bf < 2; bf++) {
            uint32_t r0 = (uint32_t)(16 * bf + qr) * USTR;
#pragma unroll
            for (int mf = 0; mf < 4; mf++) {
                int mcol = m0w + 8 * mf + 2 * qc;
                uint2 w0 = *(uint2*)(smem + r0 + mcol * 4);
                uint2 w1 = *(uint2*)(smem + r0 + 8 * USTR + mcol * 4);
                float v0 = clamp1(fmaf(-STEPC, acc[bf][mf][0], dec(w0.x)));
                float v1 = clamp1(fmaf(-STEPC, acc[bf][mf][1], dec(w0.y)));
                float v2 = clamp1(fmaf(-STEPC, acc[bf][mf][2], dec(w1.x)));
                float v3 = clamp1(fmaf(-STEPC, acc[bf][mf][3], dec(w1.y)));
                if (last) {
                    *(float2*)&out[(size_t)(cb + 16 * bf + qr) * MD + mcol] =
                        make_float2(v0, v1);
                    *(float2*)&out[(size_t)(cb + 16 * bf + qr + 8) * MD + mcol] =
                        make_float2(v2, v3);
                } else {
                    *(uint2*)(smem + r0 + mcol * 4) =
                        make_uint2(pack_u(v0), pack_u(v1));
                    *(uint2*)(smem + r0 + 8 * USTR + mcol * 4) =
                        make_uint2(pack_u(v2), pack_u(v3));
                }
            }
        }
        __syncthreads();   // u_s update visible before next iteration's reads
    }
}

extern "C" void kernel_launch(void* const* d_in, const int* in_sizes, int n_in,
                              void* d_out, int out_size) {
    // metadata order: x0, xref, H, Phi, Q
    const float* xref = (const float*)d_in[1];
    const float* H    = (const float*)d_in[2];
    const float* Phi  = (const float*)d_in[3];
    const float* Q    = (const float*)d_in[4];
    float* out        = (float*)d_out;

    cudaFuncSetAttribute(mpc_mma_kernel,
                         cudaFuncAttributeMaxDynamicSharedMemorySize, SMEM_TOTAL);

    mpc_f_kernel<<<BATCH / 4, dim3(64, 4, 1)>>>(xref, Phi, Q);
    mpc_hpack_kernel<<<MD * MD / 256, 256>>>(H);
    mpc_mma_kernel<<<BATCH / BT, THREADS, SMEM_TOTAL>>>(out);
}

// round 15
// speedup vs baseline: 4.0261x; 4.0261x over previous
#include <cuda_runtime.h>
#include <cuda_bf16.h>
#include <cstdint>

// LinearMPC via mma.sync bf16 split hi/lo — CTA-local, no clusters, no cp.async.
// u <- clip(u - s(uH + f)), 100 iters, B=2048, M=512, H symmetric.
// R15: R14 with fixed hpack grid (65536 uint4 -> 256 blocks). H pre-permuted
// into fragment order so every H load is a coalesced LDG.128. CTA = 16
// batches x full M, u packed in SMEM, register-ring H prefetch, 2 barriers/iter.

#define MD 512
#define BATCH 2048
#define BT 16
#define ITERS 100
#define STEPC 0.01f
#define THREADS 256
#define USTR 2080u            // u_s / f_s row stride bytes (520 words)
#define F_OFF 33280u          // f_s offset = 16*USTR
#define SMEM_TOTAL 66560

__device__ __align__(16) float g_f [BATCH * MD];
// Fragment-ordered packed H: index (((mb*32 + kc)*4 + mf)*32 + lane), uint4.
// lane(qr,qc) holds words { H[r][k0], H[r][k0+1], H[r][k0+8], H[r][k0+9] }
// with r = mb*32+mf*8+qr, k0 = kc*16+2*qc, each word = (bf16hi<<16)|bf16lo.
__device__ __align__(16) uint4 g_hb[MD / 32 * 32 * 4 * 32];   // 65536 uint4

__device__ __forceinline__ uint32_t prmt(uint32_t a, uint32_t b, uint32_t s) {
    uint32_t d;
    asm("prmt.b32 %0, %1, %2, %3;" : "=r"(d) : "r"(a), "r"(b), "r"(s));
    return d;
}
__device__ __forceinline__ void mma4(float* d, const uint32_t* a,
                                     const uint32_t* b) {
    asm volatile(
        "mma.sync.aligned.m16n8k16.row.col.f32.bf16.bf16.f32 "
        "{%0,%1,%2,%3}, {%4,%5,%6,%7}, {%8,%9}, {%0,%1,%2,%3};"
        : "+f"(d[0]), "+f"(d[1]), "+f"(d[2]), "+f"(d[3])
        : "r"(a[0]), "r"(a[1]), "r"(a[2]), "r"(a[3]), "r"(b[0]), "r"(b[1]));
}
__device__ __forceinline__ float clamp1(float x) {
    return fminf(fmaxf(x, -1.0f), 1.0f);
}
__device__ __forceinline__ uint32_t pack_u(float v) {
    __nv_bfloat16 h = __float2bfloat16(v);
    __nv_bfloat16 l = __float2bfloat16(v - __bfloat162float(h));
    return ((uint32_t)__bfloat16_as_ushort(h) << 16)
         | (uint32_t)__bfloat16_as_ushort(l);
}
__device__ __forceinline__ float dec(uint32_t w) {
    return __bfloat162float(__ushort_as_bfloat16((unsigned short)(w >> 16)))
         + __bfloat162float(__ushort_as_bfloat16((unsigned short)(w & 0xFFFFu)));
}

// Prologue 1: f[b, k*8+i] = -2 * Phi[k] @ Q @ (xref[b,k] - xref[b,0])
// Phi/Q staged in SMEM; 4 batches x 64 k per 256-thread block.
__global__ void mpc_f_kernel(const float* __restrict__ xref,
                             const float* __restrict__ Phi,
                             const float* __restrict__ Q) {
    __shared__ float sPhi[64 * 64];
    __shared__ float sQ[64];
    for (int i = threadIdx.x; i < 4096; i += 256) sPhi[i] = Phi[i];
    if (threadIdx.x < 64) sQ[threadIdx.x] = Q[threadIdx.x];
    __syncthreads();

    int k = threadIdx.x & 63;
    int b = blockIdx.x * 4 + (threadIdx.x >> 6);
    const float* xr = xref + (size_t)b * 65 * 8;
    float dx[8], t[8];
#pragma unroll
    for (int l = 0; l < 8; l++) dx[l] = xr[k * 8 + l] - xr[l];
#pragma unroll
    for (int j = 0; j < 8; j++) {
        float s = 0.f;
#pragma unroll
        for (int l = 0; l < 8; l++) s = fmaf(sQ[j * 8 + l], dx[l], s);
        t[j] = s;
    }
    const float* Pk = sPhi + k * 64;
#pragma unroll
    for (int i = 0; i < 8; i++) {
        float s = 0.f;
#pragma unroll
        for (int j = 0; j < 8; j++) s = fmaf(Pk[i * 8 + j], t[j], s);
        g_f[(size_t)b * MD + k * 8 + i] = -2.0f * s;
    }
}

// Prologue 2: pack+permute H into fragment-ordered g_hb (65536 threads).
__global__ void mpc_hpack_kernel(const float* __restrict__ Hm) {
    int idx = blockIdx.x * 256 + threadIdx.x;        // 0..65535
    int lane = idx & 31;
    int mf   = (idx >> 5) & 3;
    int kc   = (idx >> 7) & 31;
    int mb   = idx >> 12;
    int qr = lane >> 2, qc = lane & 3;
    int row = mb * 32 + mf * 8 + qr;
    int k0  = kc * 16 + 2 * qc;
    const float* hr = Hm + (size_t)row * MD + k0;
    uint4 v;
    v.x = pack_u(hr[0]);
    v.y = pack_u(hr[1]);
    v.z = pack_u(hr[8]);
    v.w = pack_u(hr[9]);
    g_hb[idx] = v;
}

// H-fragment prefetch: 8 coalesced LDG.128 (mb stride 4096, mf stride 32).
#define PREFETCH(BUF, KC_)                                                    \
    {                                                                         \
        const uint4* p_ = hb_base + (uint32_t)(((KC_) & 31) * 128);           \
        _Pragma("unroll")                                                     \
        for (int i_ = 0; i_ < 8; i_++)                                        \
            BUF[i_] = __ldg(p_ + (i_ >> 2) * 4096 + (i_ & 3) * 32);           \
    }

// One 16-k chunk: decode A (u, packed SMEM) + B (regs), 24 MMAs.
#define COMPUTE(BUF, KC_)                                                     \
    {                                                                         \
        const uint32_t ub_ = uAb + (uint32_t)((KC_) & 31) * 64u;              \
        uint2 wa0 = *(const uint2*)(smem + ub_);                              \
        uint2 wa2 = *(const uint2*)(smem + ub_ + 32u);                        \
        uint2 wa1 = *(const uint2*)(smem + ub_ + 8u * USTR);                  \
        uint2 wa3 = *(const uint2*)(smem + ub_ + 8u * USTR + 32u);            \
        uint32_t ah[4], al[4];                                                \
        ah[0] = prmt(wa0.x, wa0.y, 0x7632u); al[0] = prmt(wa0.x, wa0.y, 0x5410u); \
        ah[1] = prmt(wa1.x, wa1.y, 0x7632u); al[1] = prmt(wa1.x, wa1.y, 0x5410u); \
        ah[2] = prmt(wa2.x, wa2.y, 0x7632u); al[2] = prmt(wa2.x, wa2.y, 0x5410u); \
        ah[3] = prmt(wa3.x, wa3.y, 0x7632u); al[3] = prmt(wa3.x, wa3.y, 0x5410u); \
        _Pragma("unroll")                                                     \
        for (int mf_ = 0; mf_ < 8; mf_++) {                                   \
            uint32_t bh[2], bl[2];                                            \
            bh[0] = prmt(BUF[mf_].x, BUF[mf_].y, 0x7632u);                    \
            bl[0] = prmt(BUF[mf_].x, BUF[mf_].y, 0x5410u);                    \
            bh[1] = prmt(BUF[mf_].z, BUF[mf_].w, 0x7632u);                    \
            bl[1] = prmt(BUF[mf_].z, BUF[mf_].w, 0x5410u);                    \
            mma4(acc[mf_], ah, bh);                                           \
            mma4(acc[mf_], al, bh);                                           \
            mma4(acc[mf_], ah, bl);                                           \
        }                                                                     \
    }

__global__ void __launch_bounds__(THREADS, 1)
mpc_mma_kernel(float* __restrict__ out) {
    extern __shared__ char smem[];   // u_s [16][520w] @0; f_s [16][520f] @F_OFF
    const int tid = threadIdx.x, lane = tid & 31;
    const int qr = lane >> 2, qc = lane & 3;
    const int w = tid >> 5;
    const int m0w = w * 64;                 // warp's 64-wide m-slice
    const int cb = blockIdx.x * BT;

    // Stage f.
    for (int i = tid; i < BT * MD; i += THREADS) {
        int b = i >> 9, m = i & (MD - 1);
        *(float*)(smem + F_OFF + (uint32_t)b * USTR + (uint32_t)m * 4u) =
            g_f[(size_t)(cb + b) * MD + m];
    }
    __syncthreads();

    // Iteration 0: u1 = clip(-s*f), write packed u_s.
#pragma unroll
    for (int mf = 0; mf < 8; mf++) {
        int mcol = m0w + 8 * mf + 2 * qc;
        float2 f0 = *(float2*)(smem + F_OFF + (uint32_t)qr * USTR + mcol * 4);
        float2 f1 = *(float2*)(smem + F_OFF + (uint32_t)(qr + 8) * USTR + mcol * 4);
        *(uint2*)(smem + (uint32_t)qr * USTR + mcol * 4) =
            make_uint2(pack_u(clamp1(-STEPC * f0.x)), pack_u(clamp1(-STEPC * f0.y)));
        *(uint2*)(smem + (uint32_t)(qr + 8) * USTR + mcol * 4) =
            make_uint2(pack_u(clamp1(-STEPC * f1.x)), pack_u(clamp1(-STEPC * f1.y)));
    }
    __syncthreads();

    // Per-lane constant offsets.
    const uint4* hb_base = g_hb + ((uint32_t)(2 * w) * 4096u + (uint32_t)lane);
    const uint32_t uAb = (uint32_t)qr * USTR + 8u * qc;              // byte

    uint4 B0[8], B1[8];
    PREFETCH(B0, 0);
    PREFETCH(B1, 1);

    for (int it = 1; it < ITERS; it++) {
        float acc[8][4];
#pragma unroll
        for (int mf = 0; mf < 8; mf++) {
            int mcol = m0w + 8 * mf + 2 * qc;
            float2 f0 = *(float2*)(smem + F_OFF + (uint32_t)qr * USTR + mcol * 4);
            float2 f1 = *(float2*)(smem + F_OFF + (uint32_t)(qr + 8) * USTR + mcol * 4);
            acc[mf][0] = f0.x; acc[mf][1] = f0.y;
            acc[mf][2] = f1.x; acc[mf][3] = f1.y;
        }

#pragma unroll 1
        for (int kc = 0; kc < 32; kc += 2) {
            COMPUTE(B0, kc);
            PREFETCH(B0, kc + 2);     // wraps: prefetches next iter's chunk 0/1
            COMPUTE(B1, kc + 1);
            PREFETCH(B1, kc + 3);
        }

        __syncthreads();   // all warps done reading u_s this iteration

        const bool last = (it == ITERS - 1);
#pragma unroll
        for (int mf = 0; mf < 8; mf++) {
            int mcol = m0w + 8 * mf + 2 * qc;
            uint2 w0 = *(uint2*)(smem + (uint32_t)qr * USTR + mcol * 4);
            uint2 w1 = *(uint2*)(smem + (uint32_t)(qr + 8) * USTR + mcol * 4);
            float v0 = clamp1(fmaf(-STEPC, acc[mf][0], dec(w0.x)));
            float v1 = clamp1(fmaf(-STEPC, acc[mf][1], dec(w0.y)));
            float v2 = clamp1(fmaf(-STEPC, acc[mf][2], dec(w1.x)));
            float v3 = clamp1(fmaf(-STEPC, acc[mf][3], dec(w1.y)));
            if (last) {
                *(float2*)&out[(size_t)(cb + qr) * MD + mcol] = make_float2(v0, v1);
                *(float2*)&out[(size_t)(cb + qr + 8) * MD + mcol] = make_float2(v2, v3);
            } else {
                *(uint2*)(smem + (uint32_t)qr * USTR + mcol * 4) =
                    make_uint2(pack_u(v0), pack_u(v1));
                *(uint2*)(smem + (uint32_t)(qr + 8) * USTR + mcol * 4) =
                    make_uint2(pack_u(v2), pack_u(v3));
            }
        }
        __syncthreads();   // u_s update visible before next iteration's reads
    }
}

extern "C" void kernel_launch(void* const* d_in, const int* in_sizes, int n_in,
                              void* d_out, int out_size) {
    // metadata order: x0, xref, H, Phi, Q
    const float* xref = (const float*)d_in[1];
    const float* H    = (const float*)d_in[2];
    const float* Phi  = (const float*)d_in[3];
    const float* Q    = (const float*)d_in[4];
    float* out        = (float*)d_out;

    cudaFuncSetAttribute(mpc_mma_kernel,
                         cudaFuncAttributeMaxDynamicSharedMemorySize, SMEM_TOTAL);

    mpc_f_kernel<<<BATCH / 4, 256>>>(xref, Phi, Q);
    mpc_hpack_kernel<<<MD * MD / 4 / 256, 256>>>(H);   // 65536 threads
    mpc_mma_kernel<<<BATCH / BT, THREADS, SMEM_TOTAL>>>(out);
}